// round 2
// baseline (speedup 1.0000x reference)
#include <cuda_runtime.h>
#include <math.h>

// DCGRU cell: B=64, N=1024, D_IN=2, U=64, K=2 -> M=5 diffusion matrices.
// All fp32. Graph-capturable: kernel launches only, scratch in __device__ globals.

#define NN 1024
#define BB 64
#define DIN 2
#define UU 64
#define FF (DIN + UU)      // 66
#define FB (FF * BB)       // 4224
#define MMAT 5

// Scratch (HBM): ~103 MB total.
__device__ float g_x0[NN * FB];        // [N, F*B]  layout: n*FB + f*BB + b
__device__ float g_x1[2][NN * FB];     // S_s @ x0
__device__ float g_x2[2][NN * FB];     // 2*S_s@x1 - x0
__device__ float g_u[BB * NN * UU];    // update gate, (b*NN+n)*UU + j

// ---------------------------------------------------------------------------
// K1: pack x0[n, f*B + b] from inputs [B, N*DIN] and hx [B, N*U]
// ---------------------------------------------------------------------------
__global__ void build_x0_kernel(const float* __restrict__ inputs,
                                const float* __restrict__ hx) {
    int idx = blockIdx.x * blockDim.x + threadIdx.x;
    if (idx >= NN * FB) return;
    int b = idx & (BB - 1);
    int f = (idx >> 6) % FF;
    int n = idx / FB;
    float v;
    if (f < DIN) v = inputs[b * (NN * DIN) + n * DIN + f];
    else         v = hx[b * (NN * UU) + n * UU + (f - DIN)];
    g_x0[idx] = v;
}

// ---------------------------------------------------------------------------
// K2: diffusion SGEMM.  Out = S @ X   (stage 1:  g_x1[s] = S_s @ g_x0)
//                       (stage 2:  g_x2[s] = 2*(S_s @ g_x1[s]) - g_x0)
// S: [1024,1024] row-major.  X/Out: [1024, 4224] row-major.
// Tiles: BM=BN=128, BK=16, 256 threads, 8x8 per-thread microtile,
// double-buffered shared memory.
// ---------------------------------------------------------------------------
__global__ __launch_bounds__(256, 2) void diffuse_gemm_kernel(
        const float* __restrict__ S0, const float* __restrict__ S1, int stage) {
    const int s = blockIdx.z;
    const float* __restrict__ S = s ? S1 : S0;
    const float* __restrict__ X = (stage == 1) ? g_x0 : g_x1[s];
    float* __restrict__ Out     = (stage == 1) ? g_x1[s] : g_x2[s];

    const int tid = threadIdx.x;
    const int i0 = blockIdx.y * 128;
    const int j0 = blockIdx.x * 128;
    const int ty = tid >> 4;   // 0..15 : row group (8 rows each)
    const int tx = tid & 15;   // 0..15 : col group (8 cols each)

    __shared__ float As[2][16][128];   // [buf][k][i]
    __shared__ float Bs[2][16][128];   // [buf][k][j]

    float acc[8][8];
#pragma unroll
    for (int r = 0; r < 8; ++r)
#pragma unroll
        for (int c = 0; c < 8; ++c) acc[r][c] = 0.0f;

    // ---- load tile 0 ----
#pragma unroll
    for (int t = 0; t < 2; ++t) {
        int id = t * 256 + tid;
        int arow = id >> 2, ak4 = id & 3;
        float4 va = *(const float4*)&S[(i0 + arow) * NN + ak4 * 4];
        As[0][ak4 * 4 + 0][arow] = va.x;
        As[0][ak4 * 4 + 1][arow] = va.y;
        As[0][ak4 * 4 + 2][arow] = va.z;
        As[0][ak4 * 4 + 3][arow] = va.w;
        int brow = id >> 5, bc4 = id & 31;
        float4 vb = *(const float4*)&X[brow * FB + j0 + bc4 * 4];
        *(float4*)&Bs[0][brow][bc4 * 4] = vb;
    }
    __syncthreads();

    int buf = 0;
    float4 pa[2], pb[2];
    for (int kt = 0; kt < 64; ++kt) {
        if (kt < 63) {
            int k0 = (kt + 1) * 16;
#pragma unroll
            for (int t = 0; t < 2; ++t) {
                int id = t * 256 + tid;
                pa[t] = *(const float4*)&S[(i0 + (id >> 2)) * NN + k0 + (id & 3) * 4];
                pb[t] = *(const float4*)&X[(k0 + (id >> 5)) * FB + j0 + (id & 31) * 4];
            }
        }
#pragma unroll
        for (int kk = 0; kk < 16; ++kk) {
            float4 a0 = *(const float4*)&As[buf][kk][ty * 8];
            float4 a1 = *(const float4*)&As[buf][kk][ty * 8 + 4];
            float4 b0 = *(const float4*)&Bs[buf][kk][tx * 8];
            float4 b1 = *(const float4*)&Bs[buf][kk][tx * 8 + 4];
            float a[8] = {a0.x, a0.y, a0.z, a0.w, a1.x, a1.y, a1.z, a1.w};
            float bv[8] = {b0.x, b0.y, b0.z, b0.w, b1.x, b1.y, b1.z, b1.w};
#pragma unroll
            for (int r = 0; r < 8; ++r)
#pragma unroll
                for (int c = 0; c < 8; ++c)
                    acc[r][c] = fmaf(a[r], bv[c], acc[r][c]);
        }
        if (kt < 63) {
            __syncthreads();
#pragma unroll
            for (int t = 0; t < 2; ++t) {
                int id = t * 256 + tid;
                int arow = id >> 2, ak4 = id & 3;
                As[buf ^ 1][ak4 * 4 + 0][arow] = pa[t].x;
                As[buf ^ 1][ak4 * 4 + 1][arow] = pa[t].y;
                As[buf ^ 1][ak4 * 4 + 2][arow] = pa[t].z;
                As[buf ^ 1][ak4 * 4 + 3][arow] = pa[t].w;
                *(float4*)&Bs[buf ^ 1][id >> 5][(id & 31) * 4] = pb[t];
            }
            __syncthreads();
            buf ^= 1;
        }
    }

    // ---- epilogue ----
#pragma unroll
    for (int r = 0; r < 8; ++r) {
        int row = i0 + ty * 8 + r;
        long base = (long)row * FB + j0 + tx * 8;
        if (stage == 1) {
            float4 v0 = {acc[r][0], acc[r][1], acc[r][2], acc[r][3]};
            float4 v1 = {acc[r][4], acc[r][5], acc[r][6], acc[r][7]};
            *(float4*)&Out[base]     = v0;
            *(float4*)&Out[base + 4] = v1;
        } else {
            float4 p0 = *(const float4*)&g_x0[base];
            float4 p1 = *(const float4*)&g_x0[base + 4];
            float4 v0 = {2.0f * acc[r][0] - p0.x, 2.0f * acc[r][1] - p0.y,
                         2.0f * acc[r][2] - p0.z, 2.0f * acc[r][3] - p0.w};
            float4 v1 = {2.0f * acc[r][4] - p1.x, 2.0f * acc[r][5] - p1.y,
                         2.0f * acc[r][6] - p1.z, 2.0f * acc[r][7] - p1.w};
            *(float4*)&Out[base]     = v0;
            *(float4*)&Out[base + 4] = v1;
        }
    }
}

// ---------------------------------------------------------------------------
// K3: gconv1 projection + sigmoid gates.
// One block per node n. Computes Y[b, o] = sum_{f,m} Z_m[n, f*B+b] * W[f*5+m, o] + bias.
// r-gate (o<64): writes r*hx into g_x0 hidden slice (for gconv2 input).
// u-gate (o>=64): stored to g_u.
// ---------------------------------------------------------------------------
__global__ __launch_bounds__(256) void proj_gate1_kernel(
        const float* __restrict__ W, const float* __restrict__ bias,
        const float* __restrict__ hx) {
    const int n = blockIdx.x;
    const int tid = threadIdx.x;
    const int tx = tid & 15;   // o group: o = tx*8 + c (0..127)
    const int ty = tid >> 4;   // b group: b = ty*4 + r (0..63)

    const float* Z[MMAT] = {
        g_x0    + (long)n * FB,
        g_x1[0] + (long)n * FB,
        g_x2[0] + (long)n * FB,
        g_x1[1] + (long)n * FB,
        g_x2[1] + (long)n * FB };

    __shared__ float Asm[MMAT][BB];    // [m][b]
    __shared__ float Wsm[MMAT][128];   // [m][o]

    float acc[4][8];
#pragma unroll
    for (int r = 0; r < 4; ++r)
#pragma unroll
        for (int c = 0; c < 8; ++c) acc[r][c] = 0.0f;

    for (int f = 0; f < FF; ++f) {
        __syncthreads();
        // MMAT*BB = 320 > 256: strided loop (R1 bug: m=4 slice was never loaded)
        for (int i = tid; i < MMAT * BB; i += 256) {
            int m = i >> 6, b = i & 63;
            Asm[m][b] = Z[m][f * BB + b];
        }
        for (int i = tid; i < MMAT * 128; i += 256)
            Wsm[i >> 7][i & 127] = W[(f * MMAT + (i >> 7)) * 128 + (i & 127)];
        __syncthreads();
#pragma unroll
        for (int m = 0; m < MMAT; ++m) {
            float a[4], w[8];
#pragma unroll
            for (int r = 0; r < 4; ++r) a[r] = Asm[m][ty * 4 + r];
#pragma unroll
            for (int c = 0; c < 8; ++c) w[c] = Wsm[m][tx * 8 + c];
#pragma unroll
            for (int r = 0; r < 4; ++r)
#pragma unroll
                for (int c = 0; c < 8; ++c)
                    acc[r][c] = fmaf(a[r], w[c], acc[r][c]);
        }
    }
    __syncthreads();   // all reads of g_x0 row n done before we overwrite it

#pragma unroll
    for (int r = 0; r < 4; ++r) {
        int b = ty * 4 + r;
#pragma unroll
        for (int c = 0; c < 8; ++c) {
            int o = tx * 8 + c;
            float y = acc[r][c] + bias[o];
            float v = 1.0f / (1.0f + expf(-y));
            if (o < UU) {
                // r-gate: write r*hx into x0's hidden slice for gconv2
                float h = hx[b * (NN * UU) + n * UU + o];
                g_x0[(long)n * FB + (DIN + o) * BB + b] = v * h;
            } else {
                g_u[((long)b * NN + n) * UU + (o - UU)] = v;
            }
        }
    }
}

// ---------------------------------------------------------------------------
// K4: gconv2 projection + tanh + final GRU combine.
// out[b, n*U + j] = u*hx + (1-u)*tanh(y)
// ---------------------------------------------------------------------------
__global__ __launch_bounds__(256) void proj_gate2_kernel(
        const float* __restrict__ W, const float* __restrict__ bias,
        const float* __restrict__ hx, float* __restrict__ out) {
    const int n = blockIdx.x;
    const int tid = threadIdx.x;
    const int tx = tid & 15;   // o group: o = tx*4 + c (0..63)
    const int ty = tid >> 4;   // b group: b = ty*4 + r (0..63)

    const float* Z[MMAT] = {
        g_x0    + (long)n * FB,
        g_x1[0] + (long)n * FB,
        g_x2[0] + (long)n * FB,
        g_x1[1] + (long)n * FB,
        g_x2[1] + (long)n * FB };

    __shared__ float Asm[MMAT][BB];   // [m][b]
    __shared__ float Wsm[MMAT][UU];   // [m][o]

    float acc[4][4];
#pragma unroll
    for (int r = 0; r < 4; ++r)
#pragma unroll
        for (int c = 0; c < 4; ++c) acc[r][c] = 0.0f;

    for (int f = 0; f < FF; ++f) {
        __syncthreads();
        // MMAT*BB = MMAT*UU = 320 > 256: strided loops (R1 bug fix)
        for (int i = tid; i < MMAT * BB; i += 256) {
            int m = i >> 6, b = i & 63;
            Asm[m][b] = Z[m][f * BB + b];
        }
        for (int i = tid; i < MMAT * UU; i += 256) {
            int m = i >> 6, o = i & 63;
            Wsm[m][o] = W[(f * MMAT + m) * UU + o];
        }
        __syncthreads();
#pragma unroll
        for (int m = 0; m < MMAT; ++m) {
            float a[4], w[4];
#pragma unroll
            for (int r = 0; r < 4; ++r) a[r] = Asm[m][ty * 4 + r];
#pragma unroll
            for (int c = 0; c < 4; ++c) w[c] = Wsm[m][tx * 4 + c];
#pragma unroll
            for (int r = 0; r < 4; ++r)
#pragma unroll
                for (int c = 0; c < 4; ++c)
                    acc[r][c] = fmaf(a[r], w[c], acc[r][c]);
        }
    }

#pragma unroll
    for (int r = 0; r < 4; ++r) {
        int b = ty * 4 + r;
#pragma unroll
        for (int c = 0; c < 4; ++c) {
            int o = tx * 4 + c;
            float y = acc[r][c] + bias[o];
            float cc = tanhf(y);
            long hidx = (long)b * (NN * UU) + n * UU + o;
            float u = g_u[((long)b * NN + n) * UU + o];
            float h = hx[hidx];
            out[hidx] = u * h + (1.0f - u) * cc;
        }
    }
}

// ---------------------------------------------------------------------------
extern "C" void kernel_launch(void* const* d_in, const int* in_sizes, int n_in,
                              void* d_out, int out_size) {
    const float* inputs = (const float*)d_in[0];
    const float* hx     = (const float*)d_in[1];
    const float* S0     = (const float*)d_in[2];
    const float* S1     = (const float*)d_in[3];
    const float* Wo     = (const float*)d_in[4];
    const float* bo     = (const float*)d_in[5];
    const float* Wu     = (const float*)d_in[6];
    const float* bu     = (const float*)d_in[7];
    float* out = (float*)d_out;

    build_x0_kernel<<<(NN * FB + 255) / 256, 256>>>(inputs, hx);

    dim3 ggrid(FB / 128, NN / 128, 2);   // (33, 8, 2)
    // gconv 1
    diffuse_gemm_kernel<<<ggrid, 256>>>(S0, S1, 1);
    diffuse_gemm_kernel<<<ggrid, 256>>>(S0, S1, 2);
    proj_gate1_kernel<<<NN, 256>>>(Wo, bo, hx);
    // gconv 2 (x0 hidden slice now holds r*hx)
    diffuse_gemm_kernel<<<ggrid, 256>>>(S0, S1, 1);
    diffuse_gemm_kernel<<<ggrid, 256>>>(S0, S1, 2);
    proj_gate2_kernel<<<NN, 256>>>(Wu, bu, hx, out);
}

// round 3
// speedup vs baseline: 1.1573x; 1.1573x over previous
#include <cuda_runtime.h>
#include <math.h>

// DCGRU cell: B=64, N=1024, D_IN=2, U=64, K=2 -> M=5 diffusion matrices.
// All fp32. Graph-capturable: kernel launches only, scratch in __device__ globals.

#define NN 1024
#define BB 64
#define DIN 2
#define UU 64
#define FF (DIN + UU)      // 66
#define FB (FF * BB)       // 4224
#define MMAT 5
#define KTOT (FF * MMAT)   // 330
#define KT 55              // K-chunk for projection kernels (330 = 6*55)
#define NCH 6

// Scratch (HBM): ~103 MB total.
__device__ float g_x0[NN * FB];        // [N, F*B]  layout: n*FB + f*BB + b
__device__ float g_x1[2][NN * FB];     // S_s @ x0
__device__ float g_x2[2][NN * FB];     // 2*S_s@x1 - x0
__device__ float g_u[BB * NN * UU];    // update gate, (b*NN+n)*UU + j

// ---------------------------------------------------------------------------
// K1: pack x0[n, f*B + b] from inputs [B, N*DIN] and hx [B, N*U]
// ---------------------------------------------------------------------------
__global__ void build_x0_kernel(const float* __restrict__ inputs,
                                const float* __restrict__ hx) {
    int idx = blockIdx.x * blockDim.x + threadIdx.x;
    if (idx >= NN * FB) return;
    int b = idx & (BB - 1);
    int f = (idx >> 6) % FF;
    int n = idx / FB;
    float v;
    if (f < DIN) v = inputs[b * (NN * DIN) + n * DIN + f];
    else         v = hx[b * (NN * UU) + n * UU + (f - DIN)];
    g_x0[idx] = v;
}

// ---------------------------------------------------------------------------
// K2: diffusion SGEMM.  Out = S @ X   (stage 1:  g_x1[s] = S_s @ g_x0)
//                       (stage 2:  g_x2[s] = 2*(S_s @ g_x1[s]) - g_x0)
// S: [1024,1024] row-major.  X/Out: [1024, 4224] row-major.
// ---------------------------------------------------------------------------
__global__ __launch_bounds__(256, 2) void diffuse_gemm_kernel(
        const float* __restrict__ S0, const float* __restrict__ S1, int stage) {
    const int s = blockIdx.z;
    const float* __restrict__ S = s ? S1 : S0;
    const float* __restrict__ X = (stage == 1) ? g_x0 : g_x1[s];
    float* __restrict__ Out     = (stage == 1) ? g_x1[s] : g_x2[s];

    const int tid = threadIdx.x;
    const int i0 = blockIdx.y * 128;
    const int j0 = blockIdx.x * 128;
    const int ty = tid >> 4;
    const int tx = tid & 15;

    __shared__ float As[2][16][128];
    __shared__ float Bs[2][16][128];

    float acc[8][8];
#pragma unroll
    for (int r = 0; r < 8; ++r)
#pragma unroll
        for (int c = 0; c < 8; ++c) acc[r][c] = 0.0f;

#pragma unroll
    for (int t = 0; t < 2; ++t) {
        int id = t * 256 + tid;
        int arow = id >> 2, ak4 = id & 3;
        float4 va = *(const float4*)&S[(i0 + arow) * NN + ak4 * 4];
        As[0][ak4 * 4 + 0][arow] = va.x;
        As[0][ak4 * 4 + 1][arow] = va.y;
        As[0][ak4 * 4 + 2][arow] = va.z;
        As[0][ak4 * 4 + 3][arow] = va.w;
        int brow = id >> 5, bc4 = id & 31;
        float4 vb = *(const float4*)&X[brow * FB + j0 + bc4 * 4];
        *(float4*)&Bs[0][brow][bc4 * 4] = vb;
    }
    __syncthreads();

    int buf = 0;
    float4 pa[2], pb[2];
    for (int kt = 0; kt < 64; ++kt) {
        if (kt < 63) {
            int k0 = (kt + 1) * 16;
#pragma unroll
            for (int t = 0; t < 2; ++t) {
                int id = t * 256 + tid;
                pa[t] = *(const float4*)&S[(i0 + (id >> 2)) * NN + k0 + (id & 3) * 4];
                pb[t] = *(const float4*)&X[(k0 + (id >> 5)) * FB + j0 + (id & 31) * 4];
            }
        }
#pragma unroll
        for (int kk = 0; kk < 16; ++kk) {
            float4 a0 = *(const float4*)&As[buf][kk][ty * 8];
            float4 a1 = *(const float4*)&As[buf][kk][ty * 8 + 4];
            float4 b0 = *(const float4*)&Bs[buf][kk][tx * 8];
            float4 b1 = *(const float4*)&Bs[buf][kk][tx * 8 + 4];
            float a[8] = {a0.x, a0.y, a0.z, a0.w, a1.x, a1.y, a1.z, a1.w};
            float bv[8] = {b0.x, b0.y, b0.z, b0.w, b1.x, b1.y, b1.z, b1.w};
#pragma unroll
            for (int r = 0; r < 8; ++r)
#pragma unroll
                for (int c = 0; c < 8; ++c)
                    acc[r][c] = fmaf(a[r], bv[c], acc[r][c]);
        }
        if (kt < 63) {
            __syncthreads();
#pragma unroll
            for (int t = 0; t < 2; ++t) {
                int id = t * 256 + tid;
                int arow = id >> 2, ak4 = id & 3;
                As[buf ^ 1][ak4 * 4 + 0][arow] = pa[t].x;
                As[buf ^ 1][ak4 * 4 + 1][arow] = pa[t].y;
                As[buf ^ 1][ak4 * 4 + 2][arow] = pa[t].z;
                As[buf ^ 1][ak4 * 4 + 3][arow] = pa[t].w;
                *(float4*)&Bs[buf ^ 1][id >> 5][(id & 31) * 4] = pb[t];
            }
            __syncthreads();
            buf ^= 1;
        }
    }

#pragma unroll
    for (int r = 0; r < 8; ++r) {
        int row = i0 + ty * 8 + r;
        long base = (long)row * FB + j0 + tx * 8;
        if (stage == 1) {
            float4 v0 = {acc[r][0], acc[r][1], acc[r][2], acc[r][3]};
            float4 v1 = {acc[r][4], acc[r][5], acc[r][6], acc[r][7]};
            *(float4*)&Out[base]     = v0;
            *(float4*)&Out[base + 4] = v1;
        } else {
            float4 p0 = *(const float4*)&g_x0[base];
            float4 p1 = *(const float4*)&g_x0[base + 4];
            float4 v0 = {2.0f * acc[r][0] - p0.x, 2.0f * acc[r][1] - p0.y,
                         2.0f * acc[r][2] - p0.z, 2.0f * acc[r][3] - p0.w};
            float4 v1 = {2.0f * acc[r][4] - p1.x, 2.0f * acc[r][5] - p1.y,
                         2.0f * acc[r][6] - p1.z, 2.0f * acc[r][7] - p1.w};
            *(float4*)&Out[base]     = v0;
            *(float4*)&Out[base + 4] = v1;
        }
    }
}

// ---------------------------------------------------------------------------
// K3: gconv1 projection + sigmoid gates, chunked-K GEMM form.
// One block per node n: Y[b,o] = sum_kk A[kk,b] * W[kk,o],  kk = f*5+m (=W row).
// 6 chunks of KT=55 -> 12 barriers total (was 132).
// ---------------------------------------------------------------------------
__global__ __launch_bounds__(256) void proj_gate1_kernel(
        const float* __restrict__ W, const float* __restrict__ bias,
        const float* __restrict__ hx) {
    const int n = blockIdx.x;
    const int tid = threadIdx.x;
    const int tx = tid & 15;   // o group: o = tx*8 + c (0..127)
    const int ty = tid >> 4;   // b group: b = ty*4 + r (0..63)

    const float* Zp[MMAT] = {
        g_x0    + (long)n * FB,
        g_x1[0] + (long)n * FB,
        g_x2[0] + (long)n * FB,
        g_x1[1] + (long)n * FB,
        g_x2[1] + (long)n * FB };

    __shared__ float Asm[KT][BB];     // 14.1 KB
    __shared__ float Wsm[KT][128];    // 28.2 KB

    float acc[4][8];
#pragma unroll
    for (int r = 0; r < 4; ++r)
#pragma unroll
        for (int c = 0; c < 8; ++c) acc[r][c] = 0.0f;

    for (int ch = 0; ch < NCH; ++ch) {
        const int kk0 = ch * KT;
        __syncthreads();
        // A chunk: 55 rows x 16 float4
        for (int id = tid; id < KT * 16; id += 256) {
            int kl = id >> 4, b4 = id & 15;
            int kk = kk0 + kl;
            int f = kk / MMAT, m = kk - MMAT * f;
            *(float4*)&Asm[kl][b4 * 4] = *(const float4*)&Zp[m][f * BB + b4 * 4];
        }
        // W chunk: 55 rows x 32 float4 (rows are contiguous: row index == kk)
        for (int id = tid; id < KT * 32; id += 256) {
            int kl = id >> 5, o4 = id & 31;
            *(float4*)&Wsm[kl][o4 * 4] =
                *(const float4*)&W[(long)(kk0 + kl) * 128 + o4 * 4];
        }
        __syncthreads();
#pragma unroll 5
        for (int kl = 0; kl < KT; ++kl) {
            float4 a4 = *(const float4*)&Asm[kl][ty * 4];
            float4 w0 = *(const float4*)&Wsm[kl][tx * 8];
            float4 w1 = *(const float4*)&Wsm[kl][tx * 8 + 4];
            float a[4] = {a4.x, a4.y, a4.z, a4.w};
            float w[8] = {w0.x, w0.y, w0.z, w0.w, w1.x, w1.y, w1.z, w1.w};
#pragma unroll
            for (int r = 0; r < 4; ++r)
#pragma unroll
                for (int c = 0; c < 8; ++c)
                    acc[r][c] = fmaf(a[r], w[c], acc[r][c]);
        }
    }

#pragma unroll
    for (int r = 0; r < 4; ++r) {
        int b = ty * 4 + r;
#pragma unroll
        for (int c = 0; c < 8; ++c) {
            int o = tx * 8 + c;
            float y = acc[r][c] + bias[o];
            float v = 1.0f / (1.0f + expf(-y));
            if (o < UU) {
                // r-gate: write r*hx into x0's hidden slice for gconv2
                float h = hx[b * (NN * UU) + n * UU + o];
                g_x0[(long)n * FB + (DIN + o) * BB + b] = v * h;
            } else {
                g_u[((long)b * NN + n) * UU + (o - UU)] = v;
            }
        }
    }
}

// ---------------------------------------------------------------------------
// K4: gconv2 projection + tanh + final GRU combine, chunked-K GEMM form.
// ---------------------------------------------------------------------------
__global__ __launch_bounds__(256) void proj_gate2_kernel(
        const float* __restrict__ W, const float* __restrict__ bias,
        const float* __restrict__ hx, float* __restrict__ out) {
    const int n = blockIdx.x;
    const int tid = threadIdx.x;
    const int tx = tid & 15;   // o group: o = tx*4 + c (0..63)
    const int ty = tid >> 4;   // b group: b = ty*4 + r (0..63)

    const float* Zp[MMAT] = {
        g_x0    + (long)n * FB,
        g_x1[0] + (long)n * FB,
        g_x2[0] + (long)n * FB,
        g_x1[1] + (long)n * FB,
        g_x2[1] + (long)n * FB };

    __shared__ float Asm[KT][BB];    // 14.1 KB
    __shared__ float Wsm[KT][UU];    // 14.1 KB

    float acc[4][4];
#pragma unroll
    for (int r = 0; r < 4; ++r)
#pragma unroll
        for (int c = 0; c < 4; ++c) acc[r][c] = 0.0f;

    for (int ch = 0; ch < NCH; ++ch) {
        const int kk0 = ch * KT;
        __syncthreads();
        for (int id = tid; id < KT * 16; id += 256) {
            int kl = id >> 4, b4 = id & 15;
            int kk = kk0 + kl;
            int f = kk / MMAT, m = kk - MMAT * f;
            *(float4*)&Asm[kl][b4 * 4] = *(const float4*)&Zp[m][f * BB + b4 * 4];
        }
        for (int id = tid; id < KT * 16; id += 256) {
            int kl = id >> 4, o4 = id & 15;
            *(float4*)&Wsm[kl][o4 * 4] =
                *(const float4*)&W[(long)(kk0 + kl) * UU + o4 * 4];
        }
        __syncthreads();
#pragma unroll 5
        for (int kl = 0; kl < KT; ++kl) {
            float4 a4 = *(const float4*)&Asm[kl][ty * 4];
            float4 w4 = *(const float4*)&Wsm[kl][tx * 4];
            float a[4] = {a4.x, a4.y, a4.z, a4.w};
            float w[4] = {w4.x, w4.y, w4.z, w4.w};
#pragma unroll
            for (int r = 0; r < 4; ++r)
#pragma unroll
                for (int c = 0; c < 4; ++c)
                    acc[r][c] = fmaf(a[r], w[c], acc[r][c]);
        }
    }

#pragma unroll
    for (int r = 0; r < 4; ++r) {
        int b = ty * 4 + r;
#pragma unroll
        for (int c = 0; c < 4; ++c) {
            int o = tx * 4 + c;
            float y = acc[r][c] + bias[o];
            float cc = tanhf(y);
            long hidx = (long)b * (NN * UU) + n * UU + o;
            float u = g_u[((long)b * NN + n) * UU + o];
            float h = hx[hidx];
            out[hidx] = u * h + (1.0f - u) * cc;
        }
    }
}

// ---------------------------------------------------------------------------
extern "C" void kernel_launch(void* const* d_in, const int* in_sizes, int n_in,
                              void* d_out, int out_size) {
    const float* inputs = (const float*)d_in[0];
    const float* hx     = (const float*)d_in[1];
    const float* S0     = (const float*)d_in[2];
    const float* S1     = (const float*)d_in[3];
    const float* Wo     = (const float*)d_in[4];
    const float* bo     = (const float*)d_in[5];
    const float* Wu     = (const float*)d_in[6];
    const float* bu     = (const float*)d_in[7];
    float* out = (float*)d_out;

    build_x0_kernel<<<(NN * FB + 255) / 256, 256>>>(inputs, hx);

    dim3 ggrid(FB / 128, NN / 128, 2);   // (33, 8, 2)
    // gconv 1
    diffuse_gemm_kernel<<<ggrid, 256>>>(S0, S1, 1);
    diffuse_gemm_kernel<<<ggrid, 256>>>(S0, S1, 2);
    proj_gate1_kernel<<<NN, 256>>>(Wo, bo, hx);
    // gconv 2 (x0 hidden slice now holds r*hx)
    diffuse_gemm_kernel<<<ggrid, 256>>>(S0, S1, 1);
    diffuse_gemm_kernel<<<ggrid, 256>>>(S0, S1, 2);
    proj_gate2_kernel<<<NN, 256>>>(Wu, bu, hx, out);
}

// round 9
// speedup vs baseline: 1.9247x; 1.6631x over previous
#include <cuda_runtime.h>
#include <cuda_bf16.h>
#include <math.h>
#include <stdint.h>

// DCGRU cell: B=64, N=1024, D_IN=2, U=64, K=2 -> M=5 diffusion matrices.
// Diffusion GEMMs: bf16 hi/lo split-3 on mma.sync (HMMA fallback; tcgen05 is
// 'a'-gated and the harness compiles plain compute_103 PTX). fp32 accum.
// Projections fp32 (unchanged from R3).

#define NN 1024
#define BB 64
#define DIN 2
#define UU 64
#define FF (DIN + UU)      // 66
#define FB (FF * BB)       // 4224
#define MMAT 5
#define KT 55
#define NCH 6
#define CHK 64             // K per GEMM chunk
#define NCHK (NN / CHK)    // 16

// ---------------- scratch ----------------
__device__ float g_x0[NN * FB];         // [n][j]  j = f*BB+b
__device__ float g_x1[2][NN * FB];
__device__ float g_x2[2][NN * FB];
__device__ float g_u[BB * NN * UU];

__device__ __nv_bfloat16 g_Sh[2][NN * NN];   // bf16 hi of supports
__device__ __nv_bfloat16 g_Sl[2][NN * NN];   // bf16 lo
__device__ __nv_bfloat16 g_x0Th[FB * NN];    // x0 transposed [j][n], hi
__device__ __nv_bfloat16 g_x0Tl[FB * NN];
__device__ __nv_bfloat16 g_x1Th[2][FB * NN];
__device__ __nv_bfloat16 g_x1Tl[2][FB * NN];

// ---------------- PTX helpers (sm_80-class only; no 'a'-gated ops) --------
__device__ __forceinline__ uint32_t smem_u32(const void* p) {
    uint32_t a;
    asm("{ .reg .u64 t; cvta.to.shared.u64 t, %1; cvt.u32.u64 %0, t; }"
        : "=r"(a) : "l"(p));
    return a;
}
__device__ __forceinline__ void cp16(uint32_t saddr, const void* gptr) {
    asm volatile("cp.async.cg.shared.global [%0], [%1], 16;"
                 :: "r"(saddr), "l"(gptr));
}
#define CP_COMMIT() asm volatile("cp.async.commit_group;" ::: "memory")
#define CP_WAIT(n)  asm volatile("cp.async.wait_group %0;" :: "n"(n) : "memory")

__device__ __forceinline__ void ldsm4(uint32_t* r, uint32_t addr) {
    asm volatile("ldmatrix.sync.aligned.m8n8.x4.shared.b16 {%0,%1,%2,%3}, [%4];"
                 : "=r"(r[0]), "=r"(r[1]), "=r"(r[2]), "=r"(r[3]) : "r"(addr));
}
__device__ __forceinline__ void mma_bf16(float* c, const uint32_t* a,
                                         uint32_t b0, uint32_t b1) {
    asm volatile(
        "mma.sync.aligned.m16n8k16.row.col.f32.bf16.bf16.f32 "
        "{%0,%1,%2,%3}, {%4,%5,%6,%7}, {%8,%9}, {%0,%1,%2,%3};"
        : "+f"(c[0]), "+f"(c[1]), "+f"(c[2]), "+f"(c[3])
        : "r"(a[0]), "r"(a[1]), "r"(a[2]), "r"(a[3]), "r"(b0), "r"(b1));
}
__device__ __forceinline__ uint32_t sw128(uint32_t off) {
    return off ^ ((off >> 3) & 0x70);
}

// ---------------------------------------------------------------------------
// K1: pack x0[n][f*BB+b]
// ---------------------------------------------------------------------------
__global__ void build_x0_kernel(const float* __restrict__ inputs,
                                const float* __restrict__ hx) {
    int idx = blockIdx.x * blockDim.x + threadIdx.x;
    if (idx >= NN * FB) return;
    int b = idx & (BB - 1);
    int f = (idx >> 6) % FF;
    int n = idx / FB;
    float v;
    if (f < DIN) v = inputs[b * (NN * DIN) + n * DIN + f];
    else         v = hx[b * (NN * UU) + n * UU + (f - DIN)];
    g_x0[idx] = v;
}

// ---------------------------------------------------------------------------
// K2: split supports to bf16 hi/lo
// ---------------------------------------------------------------------------
__global__ void splitS_kernel(const float* __restrict__ S0,
                              const float* __restrict__ S1) {
    int s = blockIdx.y;
    int i = blockIdx.x * 256 + threadIdx.x;
    if (i >= NN * NN) return;
    float v = (s ? S1 : S0)[i];
    __nv_bfloat16 h = __float2bfloat16(v);
    g_Sh[s][i] = h;
    g_Sl[s][i] = __float2bfloat16(v - __bfloat162float(h));
}

// ---------------------------------------------------------------------------
// K3: transpose + split: fp32 [NN][FB] -> bf16 hi/lo [FB][NN]
// ---------------------------------------------------------------------------
__global__ void tsplit_kernel(int which) {
    const float* src = (which == 0) ? g_x0 : (which == 1 ? g_x1[0] : g_x1[1]);
    __nv_bfloat16* dh = (which == 0) ? g_x0Th : (which == 1 ? g_x1Th[0] : g_x1Th[1]);
    __nv_bfloat16* dl = (which == 0) ? g_x0Tl : (which == 1 ? g_x1Tl[0] : g_x1Tl[1]);
    __shared__ float t[64][65];
    int j0 = blockIdx.x * 64, n0 = blockIdx.y * 64;
    int tid = threadIdx.x;
    for (int id = tid; id < 64 * 16; id += 256) {
        int nl = id >> 4, j4 = id & 15;
        float4 v = *(const float4*)&src[(long)(n0 + nl) * FB + j0 + j4 * 4];
        t[nl][j4 * 4 + 0] = v.x; t[nl][j4 * 4 + 1] = v.y;
        t[nl][j4 * 4 + 2] = v.z; t[nl][j4 * 4 + 3] = v.w;
    }
    __syncthreads();
    int jl = tid >> 2, q = tid & 3;
    long ro = (long)(j0 + jl) * NN + n0 + q * 16;
#pragma unroll
    for (int u = 0; u < 16; ++u) {
        float v = t[q * 16 + u][jl];
        __nv_bfloat16 h = __float2bfloat16(v);
        dh[ro + u] = h;
        dl[ro + u] = __float2bfloat16(v - __bfloat162float(h));
    }
}

// ---------------------------------------------------------------------------
// K4: HMMA diffusion GEMM.  D[i,j] = sum_k S[i,k] * XT[j,k]
// 3 bf16 split MMAs (hh, hl, lh), fp32 accum.
// Block 128x128, 8 warps of 64x32, K-chunks of 64 double-buffered (cp.async).
// stage 1: XT = x0T,  out g_x1[s] = D
// stage 2: XT = x1T[s], out g_x2[s] = 2*D - g_x0
// SMEM: 2 buffers x (Ah,Al,Bh,Bl each 128x64 bf16 = 16KB) = 131072 B.
// ---------------------------------------------------------------------------
#define BUF_STRIDE 65536
#define OFF_AH 0
#define OFF_AL 16384
#define OFF_BH 32768
#define OFF_BL 49152
#define SMEM_HM (2 * BUF_STRIDE)

__global__ void __launch_bounds__(256) diffuse_hmma_kernel(int stage) {
    extern __shared__ char dsm[];
    const int s  = blockIdx.z;
    const int i0 = blockIdx.y * 128;
    const int j0 = blockIdx.x * 128;
    const int tid  = threadIdx.x;
    const int wid  = tid >> 5;
    const int lane = tid & 31;

    const __nv_bfloat16* __restrict__ Ah = g_Sh[s] + (long)i0 * NN;
    const __nv_bfloat16* __restrict__ Al = g_Sl[s] + (long)i0 * NN;
    const __nv_bfloat16* __restrict__ Bh = ((stage == 1) ? g_x0Th : g_x1Th[s]) + (long)j0 * NN;
    const __nv_bfloat16* __restrict__ Bl = ((stage == 1) ? g_x0Tl : g_x1Tl[s]) + (long)j0 * NN;

    const uint32_t sb = smem_u32(dsm);

    // ---- async chunk loader: chunk c -> buffer buf ----
    auto load_chunk = [&](int c, int buf) {
        const uint32_t bb = sb + buf * BUF_STRIDE;
        const __nv_bfloat16* srcs[4] = {Ah, Al, Bh, Bl};
        const uint32_t aoff[4] = {OFF_AH, OFF_AL, OFF_BH, OFF_BL};
#pragma unroll
        for (int a4 = 0; a4 < 4; ++a4) {
            const __nv_bfloat16* src = srcs[a4] + c * CHK;
#pragma unroll
            for (int it = 0; it < 4; ++it) {
                int id = it * 256 + tid;
                int r = id >> 3, ck = id & 7;
                uint32_t so = sw128((uint32_t)(r * 128 + ck * 16));
                cp16(bb + aoff[a4] + so, src + (long)r * NN + ck * 8);
            }
        }
    };

    // ---- per-lane ldmatrix address bases (swizzle applied per step) ----
    const int grp = lane >> 3, lr = lane & 7;
    const int rowA = ((grp & 1) << 3) + lr;        // + wi + mt*16
    const int kplA = (grp >> 1) << 4;
    const int rowB = ((grp >> 1) << 3) + lr;       // + wj + g*16
    const int kplB = (grp & 1) << 4;
    const int wi = (wid & 1) * 64;
    const int wj = (wid >> 1) * 32;
    uint32_t offA[4], offB[2];
#pragma unroll
    for (int mt = 0; mt < 4; ++mt)
        offA[mt] = (uint32_t)((wi + mt * 16 + rowA) * 128 + kplA);
#pragma unroll
    for (int g = 0; g < 2; ++g)
        offB[g] = (uint32_t)((wj + g * 16 + rowB) * 128 + kplB);

    float acc[4][4][4];
#pragma unroll
    for (int mt = 0; mt < 4; ++mt)
#pragma unroll
        for (int nt = 0; nt < 4; ++nt)
#pragma unroll
            for (int q = 0; q < 4; ++q) acc[mt][nt][q] = 0.0f;

    load_chunk(0, 0); CP_COMMIT();
    load_chunk(1, 1); CP_COMMIT();

    for (int c = 0; c < NCHK; ++c) {
        if (c < NCHK - 1) { CP_WAIT(1); } else { CP_WAIT(0); }
        __syncthreads();
        const uint32_t bb = sb + (c & 1) * BUF_STRIDE;
#pragma unroll
        for (int st = 0; st < 4; ++st) {
            const uint32_t kb = st * 32;
            uint32_t ah[4][4], al[4][4], bh[2][4], bl[2][4];
#pragma unroll
            for (int mt = 0; mt < 4; ++mt) {
                uint32_t o = sw128(offA[mt] + kb);
                ldsm4(ah[mt], bb + OFF_AH + o);
                ldsm4(al[mt], bb + OFF_AL + o);
            }
#pragma unroll
            for (int g = 0; g < 2; ++g) {
                uint32_t o = sw128(offB[g] + kb);
                ldsm4(bh[g], bb + OFF_BH + o);
                ldsm4(bl[g], bb + OFF_BL + o);
            }
#pragma unroll
            for (int mt = 0; mt < 4; ++mt)
#pragma unroll
                for (int nt = 0; nt < 4; ++nt) {
                    const int g = nt >> 1, p = (nt & 1) * 2;
                    mma_bf16(acc[mt][nt], ah[mt], bh[g][p], bh[g][p + 1]);
                    mma_bf16(acc[mt][nt], ah[mt], bl[g][p], bl[g][p + 1]);
                    mma_bf16(acc[mt][nt], al[mt], bh[g][p], bh[g][p + 1]);
                }
        }
        __syncthreads();
        if (c + 2 < NCHK) { load_chunk(c + 2, c & 1); CP_COMMIT(); }
    }

    // ---- epilogue ----
    float* __restrict__ dst = (stage == 1) ? g_x1[s] : g_x2[s];
    const int er = lane >> 2, ec = (lane & 3) * 2;
#pragma unroll
    for (int mt = 0; mt < 4; ++mt) {
#pragma unroll
        for (int nt = 0; nt < 4; ++nt) {
            const int gi = i0 + wi + mt * 16 + er;
            const int gj = j0 + wj + nt * 8 + ec;
            const float* a = acc[mt][nt];
            if (stage == 1) {
                *(float2*)&dst[(long)gi * FB + gj]       = make_float2(a[0], a[1]);
                *(float2*)&dst[(long)(gi + 8) * FB + gj] = make_float2(a[2], a[3]);
            } else {
                float2 p0 = *(const float2*)&g_x0[(long)gi * FB + gj];
                float2 p1 = *(const float2*)&g_x0[(long)(gi + 8) * FB + gj];
                *(float2*)&dst[(long)gi * FB + gj] =
                    make_float2(2.0f * a[0] - p0.x, 2.0f * a[1] - p0.y);
                *(float2*)&dst[(long)(gi + 8) * FB + gj] =
                    make_float2(2.0f * a[2] - p1.x, 2.0f * a[3] - p1.y);
            }
        }
    }
}

// ---------------------------------------------------------------------------
// K5: gconv1 projection + sigmoid gates (unchanged from R3)
// ---------------------------------------------------------------------------
__global__ __launch_bounds__(256) void proj_gate1_kernel(
        const float* __restrict__ W, const float* __restrict__ bias,
        const float* __restrict__ hx) {
    const int n = blockIdx.x;
    const int tid = threadIdx.x;
    const int tx = tid & 15;
    const int ty = tid >> 4;

    const float* Zp[MMAT] = {
        g_x0    + (long)n * FB,
        g_x1[0] + (long)n * FB,
        g_x2[0] + (long)n * FB,
        g_x1[1] + (long)n * FB,
        g_x2[1] + (long)n * FB };

    __shared__ float Asm[KT][BB];
    __shared__ float Wsm[KT][128];

    float acc[4][8];
#pragma unroll
    for (int r = 0; r < 4; ++r)
#pragma unroll
        for (int c = 0; c < 8; ++c) acc[r][c] = 0.0f;

    for (int ch = 0; ch < NCH; ++ch) {
        const int kk0 = ch * KT;
        __syncthreads();
        for (int id = tid; id < KT * 16; id += 256) {
            int kl = id >> 4, b4 = id & 15;
            int kk = kk0 + kl;
            int f = kk / MMAT, m = kk - MMAT * f;
            *(float4*)&Asm[kl][b4 * 4] = *(const float4*)&Zp[m][f * BB + b4 * 4];
        }
        for (int id = tid; id < KT * 32; id += 256) {
            int kl = id >> 5, o4 = id & 31;
            *(float4*)&Wsm[kl][o4 * 4] =
                *(const float4*)&W[(long)(kk0 + kl) * 128 + o4 * 4];
        }
        __syncthreads();
#pragma unroll 5
        for (int kl = 0; kl < KT; ++kl) {
            float4 a4 = *(const float4*)&Asm[kl][ty * 4];
            float4 w0 = *(const float4*)&Wsm[kl][tx * 8];
            float4 w1 = *(const float4*)&Wsm[kl][tx * 8 + 4];
            float a[4] = {a4.x, a4.y, a4.z, a4.w};
            float w[8] = {w0.x, w0.y, w0.z, w0.w, w1.x, w1.y, w1.z, w1.w};
#pragma unroll
            for (int r = 0; r < 4; ++r)
#pragma unroll
                for (int c = 0; c < 8; ++c)
                    acc[r][c] = fmaf(a[r], w[c], acc[r][c]);
        }
    }

#pragma unroll
    for (int r = 0; r < 4; ++r) {
        int b = ty * 4 + r;
#pragma unroll
        for (int c = 0; c < 8; ++c) {
            int o = tx * 8 + c;
            float y = acc[r][c] + bias[o];
            float v = 1.0f / (1.0f + expf(-y));
            if (o < UU) {
                float h = hx[b * (NN * UU) + n * UU + o];
                g_x0[(long)n * FB + (DIN + o) * BB + b] = v * h;
            } else {
                g_u[((long)b * NN + n) * UU + (o - UU)] = v;
            }
        }
    }
}

// ---------------------------------------------------------------------------
// K6: gconv2 projection + tanh + GRU combine (unchanged from R3)
// ---------------------------------------------------------------------------
__global__ __launch_bounds__(256) void proj_gate2_kernel(
        const float* __restrict__ W, const float* __restrict__ bias,
        const float* __restrict__ hx, float* __restrict__ out) {
    const int n = blockIdx.x;
    const int tid = threadIdx.x;
    const int tx = tid & 15;
    const int ty = tid >> 4;

    const float* Zp[MMAT] = {
        g_x0    + (long)n * FB,
        g_x1[0] + (long)n * FB,
        g_x2[0] + (long)n * FB,
        g_x1[1] + (long)n * FB,
        g_x2[1] + (long)n * FB };

    __shared__ float Asm[KT][BB];
    __shared__ float Wsm[KT][UU];

    float acc[4][4];
#pragma unroll
    for (int r = 0; r < 4; ++r)
#pragma unroll
        for (int c = 0; c < 4; ++c) acc[r][c] = 0.0f;

    for (int ch = 0; ch < NCH; ++ch) {
        const int kk0 = ch * KT;
        __syncthreads();
        for (int id = tid; id < KT * 16; id += 256) {
            int kl = id >> 4, b4 = id & 15;
            int kk = kk0 + kl;
            int f = kk / MMAT, m = kk - MMAT * f;
            *(float4*)&Asm[kl][b4 * 4] = *(const float4*)&Zp[m][f * BB + b4 * 4];
        }
        for (int id = tid; id < KT * 16; id += 256) {
            int kl = id >> 4, o4 = id & 15;
            *(float4*)&Wsm[kl][o4 * 4] =
                *(const float4*)&W[(long)(kk0 + kl) * UU + o4 * 4];
        }
        __syncthreads();
#pragma unroll 5
        for (int kl = 0; kl < KT; ++kl) {
            float4 a4 = *(const float4*)&Asm[kl][ty * 4];
            float4 w4 = *(const float4*)&Wsm[kl][tx * 4];
            float a[4] = {a4.x, a4.y, a4.z, a4.w};
            float w[4] = {w4.x, w4.y, w4.z, w4.w};
#pragma unroll
            for (int r = 0; r < 4; ++r)
#pragma unroll
                for (int c = 0; c < 4; ++c)
                    acc[r][c] = fmaf(a[r], w[c], acc[r][c]);
        }
    }

#pragma unroll
    for (int r = 0; r < 4; ++r) {
        int b = ty * 4 + r;
#pragma unroll
        for (int c = 0; c < 4; ++c) {
            int o = tx * 4 + c;
            float y = acc[r][c] + bias[o];
            float cc = tanhf(y);
            long hidx = (long)b * (NN * UU) + n * UU + o;
            float u = g_u[((long)b * NN + n) * UU + o];
            float h = hx[hidx];
            out[hidx] = u * h + (1.0f - u) * cc;
        }
    }
}

// ---------------------------------------------------------------------------
extern "C" void kernel_launch(void* const* d_in, const int* in_sizes, int n_in,
                              void* d_out, int out_size) {
    const float* inputs = (const float*)d_in[0];
    const float* hx     = (const float*)d_in[1];
    const float* S0     = (const float*)d_in[2];
    const float* S1     = (const float*)d_in[3];
    const float* Wo     = (const float*)d_in[4];
    const float* bo     = (const float*)d_in[5];
    const float* Wu     = (const float*)d_in[6];
    const float* bu     = (const float*)d_in[7];
    float* out = (float*)d_out;

    cudaFuncSetAttribute(diffuse_hmma_kernel,
                         cudaFuncAttributeMaxDynamicSharedMemorySize, SMEM_HM);

    dim3 tgrid(FB / 64, NN / 64);        // (66, 16)
    dim3 mgrid(FB / 128, NN / 128, 2);   // (33, 8, 2)

    build_x0_kernel<<<(NN * FB + 255) / 256, 256>>>(inputs, hx);
    splitS_kernel<<<dim3((NN * NN + 255) / 256, 2), 256>>>(S0, S1);

    // gconv 1
    tsplit_kernel<<<tgrid, 256>>>(0);
    diffuse_hmma_kernel<<<mgrid, 256, SMEM_HM>>>(1);
    tsplit_kernel<<<tgrid, 256>>>(1);
    tsplit_kernel<<<tgrid, 256>>>(2);
    diffuse_hmma_kernel<<<mgrid, 256, SMEM_HM>>>(2);
    proj_gate1_kernel<<<NN, 256>>>(Wo, bo, hx);

    // gconv 2 (x0 hidden slice now holds r*hx)
    tsplit_kernel<<<tgrid, 256>>>(0);
    diffuse_hmma_kernel<<<mgrid, 256, SMEM_HM>>>(1);
    tsplit_kernel<<<tgrid, 256>>>(1);
    tsplit_kernel<<<tgrid, 256>>>(2);
    diffuse_hmma_kernel<<<mgrid, 256, SMEM_HM>>>(2);
    proj_gate2_kernel<<<NN, 256>>>(Wu, bu, hx, out);
}

// round 16
// speedup vs baseline: 1.9787x; 1.0281x over previous
#include <cuda_runtime.h>
#include <cuda_bf16.h>
#include <math.h>
#include <stdint.h>

// DCGRU cell: B=64, N=1024, D_IN=2, U=64, K=2 -> M=5 diffusion matrices.
// Diffusion GEMMs: bf16 hi/lo split-3 on mma.sync (HMMA), fp32 accum.
// R10/R16: CHK=32 (2 CTA/SM on GEMM), proj kernels multi-node 8x8 microtile.

#define NN 1024
#define BB 64
#define DIN 2
#define UU 64
#define FF (DIN + UU)      // 66
#define FB (FF * BB)       // 4224
#define MMAT 5
#define KT 55
#define NCH 6
#define CHK 32             // K per GEMM chunk
#define NCHK (NN / CHK)    // 32

// ---------------- scratch ----------------
__device__ float g_x0[NN * FB];         // [n][j]  j = f*BB+b
__device__ float g_x1[2][NN * FB];
__device__ float g_x2[2][NN * FB];
__device__ float g_u[BB * NN * UU];

__device__ __nv_bfloat16 g_Sh[2][NN * NN];
__device__ __nv_bfloat16 g_Sl[2][NN * NN];
__device__ __nv_bfloat16 g_x0Th[FB * NN];    // transposed [j][n]
__device__ __nv_bfloat16 g_x0Tl[FB * NN];
__device__ __nv_bfloat16 g_x1Th[2][FB * NN];
__device__ __nv_bfloat16 g_x1Tl[2][FB * NN];

// ---------------- PTX helpers (no 'a'-gated ops) ----------------
__device__ __forceinline__ uint32_t smem_u32(const void* p) {
    uint32_t a;
    asm("{ .reg .u64 t; cvta.to.shared.u64 t, %1; cvt.u32.u64 %0, t; }"
        : "=r"(a) : "l"(p));
    return a;
}
__device__ __forceinline__ void cp16(uint32_t saddr, const void* gptr) {
    asm volatile("cp.async.cg.shared.global [%0], [%1], 16;"
                 :: "r"(saddr), "l"(gptr));
}
#define CP_COMMIT() asm volatile("cp.async.commit_group;" ::: "memory")
#define CP_WAIT(n)  asm volatile("cp.async.wait_group %0;" :: "n"(n) : "memory")

__device__ __forceinline__ void ldsm4(uint32_t* r, uint32_t addr) {
    asm volatile("ldmatrix.sync.aligned.m8n8.x4.shared.b16 {%0,%1,%2,%3}, [%4];"
                 : "=r"(r[0]), "=r"(r[1]), "=r"(r[2]), "=r"(r[3]) : "r"(addr));
}
__device__ __forceinline__ void mma_bf16(float* c, const uint32_t* a,
                                         uint32_t b0, uint32_t b1) {
    asm volatile(
        "mma.sync.aligned.m16n8k16.row.col.f32.bf16.bf16.f32 "
        "{%0,%1,%2,%3}, {%4,%5,%6,%7}, {%8,%9}, {%0,%1,%2,%3};"
        : "+f"(c[0]), "+f"(c[1]), "+f"(c[2]), "+f"(c[3])
        : "r"(a[0]), "r"(a[1]), "r"(a[2]), "r"(a[3]), "r"(b0), "r"(b1));
}
// 64B-row swizzle: 16B unit column XOR (row>>1)&3 (2-way within ldmatrix tile)
__device__ __forceinline__ uint32_t sw64x(uint32_t off) {
    return off ^ (((off >> 7) & 3) << 4);
}

// ---------------------------------------------------------------------------
// K1: pack x0[n][f*BB+b]
// ---------------------------------------------------------------------------
__global__ void build_x0_kernel(const float* __restrict__ inputs,
                                const float* __restrict__ hx) {
    int idx = blockIdx.x * blockDim.x + threadIdx.x;
    if (idx >= NN * FB) return;
    int b = idx & (BB - 1);
    int f = (idx >> 6) % FF;
    int n = idx / FB;
    float v;
    if (f < DIN) v = inputs[b * (NN * DIN) + n * DIN + f];
    else         v = hx[b * (NN * UU) + n * UU + (f - DIN)];
    g_x0[idx] = v;
}

// ---------------------------------------------------------------------------
// K2: split supports to bf16 hi/lo
// ---------------------------------------------------------------------------
__global__ void splitS_kernel(const float* __restrict__ S0,
                              const float* __restrict__ S1) {
    int s = blockIdx.y;
    int i = blockIdx.x * 256 + threadIdx.x;
    if (i >= NN * NN) return;
    float v = (s ? S1 : S0)[i];
    __nv_bfloat16 h = __float2bfloat16(v);
    g_Sh[s][i] = h;
    g_Sl[s][i] = __float2bfloat16(v - __bfloat162float(h));
}

// ---------------------------------------------------------------------------
// K3: transpose + split: fp32 [NN][FB] -> bf16 hi/lo [FB][NN]
// ---------------------------------------------------------------------------
__global__ void tsplit_kernel(int which) {
    const float* src = (which == 0) ? g_x0 : (which == 1 ? g_x1[0] : g_x1[1]);
    __nv_bfloat16* dh = (which == 0) ? g_x0Th : (which == 1 ? g_x1Th[0] : g_x1Th[1]);
    __nv_bfloat16* dl = (which == 0) ? g_x0Tl : (which == 1 ? g_x1Tl[0] : g_x1Tl[1]);
    __shared__ float t[64][65];
    int j0 = blockIdx.x * 64, n0 = blockIdx.y * 64;
    int tid = threadIdx.x;
    for (int id = tid; id < 64 * 16; id += 256) {
        int nl = id >> 4, j4 = id & 15;
        float4 v = *(const float4*)&src[(long)(n0 + nl) * FB + j0 + j4 * 4];
        t[nl][j4 * 4 + 0] = v.x; t[nl][j4 * 4 + 1] = v.y;
        t[nl][j4 * 4 + 2] = v.z; t[nl][j4 * 4 + 3] = v.w;
    }
    __syncthreads();
    int jl = tid >> 2, q = tid & 3;
    long ro = (long)(j0 + jl) * NN + n0 + q * 16;
#pragma unroll
    for (int u = 0; u < 16; ++u) {
        float v = t[q * 16 + u][jl];
        __nv_bfloat16 h = __float2bfloat16(v);
        dh[ro + u] = h;
        dl[ro + u] = __float2bfloat16(v - __bfloat162float(h));
    }
}

// ---------------------------------------------------------------------------
// K4: HMMA diffusion GEMM.  D[i,j] = sum_k S[i,k] * XT[j,k]
// Block 128x128, 8 warps of 64x32, K-chunks of 32 double-buffered.
// SMEM: 2 x (Ah,Al,Bh,Bl each 128x32 bf16 = 8KB) = 65536 B -> 2 CTA/SM.
// ---------------------------------------------------------------------------
#define BUF_STRIDE 32768
#define OFF_AH 0
#define OFF_AL 8192
#define OFF_BH 16384
#define OFF_BL 24576
#define SMEM_HM (2 * BUF_STRIDE)

__global__ void __launch_bounds__(256, 2) diffuse_hmma_kernel(int stage) {
    extern __shared__ char dsm[];
    const int s  = blockIdx.z;
    const int i0 = blockIdx.y * 128;
    const int j0 = blockIdx.x * 128;
    const int tid  = threadIdx.x;
    const int wid  = tid >> 5;
    const int lane = tid & 31;

    const __nv_bfloat16* __restrict__ Ah = g_Sh[s] + (long)i0 * NN;
    const __nv_bfloat16* __restrict__ Al = g_Sl[s] + (long)i0 * NN;
    const __nv_bfloat16* __restrict__ Bh = ((stage == 1) ? g_x0Th : g_x1Th[s]) + (long)j0 * NN;
    const __nv_bfloat16* __restrict__ Bl = ((stage == 1) ? g_x0Tl : g_x1Tl[s]) + (long)j0 * NN;

    const uint32_t sb = smem_u32(dsm);

    auto load_chunk = [&](int c, int buf) {
        const uint32_t bb = sb + buf * BUF_STRIDE;
        const __nv_bfloat16* srcs[4] = {Ah, Al, Bh, Bl};
        const uint32_t aoff[4] = {OFF_AH, OFF_AL, OFF_BH, OFF_BL};
#pragma unroll
        for (int a4 = 0; a4 < 4; ++a4) {
            const __nv_bfloat16* src = srcs[a4] + c * CHK;
#pragma unroll
            for (int it = 0; it < 2; ++it) {
                int id = it * 256 + tid;            // 0..511
                int r = id >> 2, ck = id & 3;       // 128 rows x 4 x 16B
                uint32_t so = sw64x((uint32_t)(r * 64 + ck * 16));
                cp16(bb + aoff[a4] + so, src + (long)r * NN + ck * 8);
            }
        }
    };

    const int grp = lane >> 3, lr = lane & 7;
    const int rowA = ((grp & 1) << 3) + lr;
    const int kplA = (grp >> 1) << 4;
    const int rowB = ((grp >> 1) << 3) + lr;
    const int kplB = (grp & 1) << 4;
    const int wi = (wid & 1) * 64;
    const int wj = (wid >> 1) * 32;
    uint32_t offA[4], offB[2];
#pragma unroll
    for (int mt = 0; mt < 4; ++mt)
        offA[mt] = (uint32_t)((wi + mt * 16 + rowA) * 64 + kplA);
#pragma unroll
    for (int g = 0; g < 2; ++g)
        offB[g] = (uint32_t)((wj + g * 16 + rowB) * 64 + kplB);

    float acc[4][4][4];
#pragma unroll
    for (int mt = 0; mt < 4; ++mt)
#pragma unroll
        for (int nt = 0; nt < 4; ++nt)
#pragma unroll
            for (int q = 0; q < 4; ++q) acc[mt][nt][q] = 0.0f;

    load_chunk(0, 0); CP_COMMIT();
    load_chunk(1, 1); CP_COMMIT();

    for (int c = 0; c < NCHK; ++c) {
        if (c < NCHK - 1) { CP_WAIT(1); } else { CP_WAIT(0); }
        __syncthreads();
        const uint32_t bb = sb + (c & 1) * BUF_STRIDE;
#pragma unroll
        for (int st = 0; st < 2; ++st) {
            const uint32_t kb = st * 32;
            uint32_t ah[4][4], al[4][4], bh[2][4], bl[2][4];
#pragma unroll
            for (int mt = 0; mt < 4; ++mt) {
                uint32_t o = sw64x(offA[mt] + kb);
                ldsm4(ah[mt], bb + OFF_AH + o);
                ldsm4(al[mt], bb + OFF_AL + o);
            }
#pragma unroll
            for (int g = 0; g < 2; ++g) {
                uint32_t o = sw64x(offB[g] + kb);
                ldsm4(bh[g], bb + OFF_BH + o);
                ldsm4(bl[g], bb + OFF_BL + o);
            }
#pragma unroll
            for (int mt = 0; mt < 4; ++mt)
#pragma unroll
                for (int nt = 0; nt < 4; ++nt) {
                    const int g = nt >> 1, p = (nt & 1) * 2;
                    mma_bf16(acc[mt][nt], ah[mt], bh[g][p], bh[g][p + 1]);
                    mma_bf16(acc[mt][nt], ah[mt], bl[g][p], bl[g][p + 1]);
                    mma_bf16(acc[mt][nt], al[mt], bh[g][p], bh[g][p + 1]);
                }
        }
        __syncthreads();
        if (c + 2 < NCHK) { load_chunk(c + 2, c & 1); CP_COMMIT(); }
    }

    float* __restrict__ dst = (stage == 1) ? g_x1[s] : g_x2[s];
    const int er = lane >> 2, ec = (lane & 3) * 2;
#pragma unroll
    for (int mt = 0; mt < 4; ++mt) {
#pragma unroll
        for (int nt = 0; nt < 4; ++nt) {
            const int gi = i0 + wi + mt * 16 + er;
            const int gj = j0 + wj + nt * 8 + ec;
            const float* a = acc[mt][nt];
            if (stage == 1) {
                *(float2*)&dst[(long)gi * FB + gj]       = make_float2(a[0], a[1]);
                *(float2*)&dst[(long)(gi + 8) * FB + gj] = make_float2(a[2], a[3]);
            } else {
                float2 p0 = *(const float2*)&g_x0[(long)gi * FB + gj];
                float2 p1 = *(const float2*)&g_x0[(long)(gi + 8) * FB + gj];
                *(float2*)&dst[(long)gi * FB + gj] =
                    make_float2(2.0f * a[0] - p0.x, 2.0f * a[1] - p0.y);
                *(float2*)&dst[(long)(gi + 8) * FB + gj] =
                    make_float2(2.0f * a[2] - p1.x, 2.0f * a[3] - p1.y);
            }
        }
    }
}

// ---------------------------------------------------------------------------
// K5: gconv1 projection + sigmoid gates.  2 nodes/block, 8x8 microtile.
// dyn smem: Asm[KT][128] + Wsm[KT][128] = 56320 B
// ---------------------------------------------------------------------------
__global__ __launch_bounds__(256) void proj_gate1_kernel(
        const float* __restrict__ W, const float* __restrict__ bias,
        const float* __restrict__ hx) {
    extern __shared__ float psm[];
    float (*Asm)[128] = (float(*)[128])psm;
    float (*Wsm)[128] = (float(*)[128])(psm + KT * 128);

    const int n0 = blockIdx.x * 2;
    const int tid = threadIdx.x;
    const int tx = tid & 15;   // o group: o = tx*8 + c
    const int ty = tid >> 4;   // brow group: brow = ty*8 + r (0..127)

    const float* Zp[2][MMAT];
#pragma unroll
    for (int nd = 0; nd < 2; ++nd) {
        long base = (long)(n0 + nd) * FB;
        Zp[nd][0] = g_x0 + base;   Zp[nd][1] = g_x1[0] + base;
        Zp[nd][2] = g_x2[0] + base; Zp[nd][3] = g_x1[1] + base;
        Zp[nd][4] = g_x2[1] + base;
    }

    float acc[8][8];
#pragma unroll
    for (int r = 0; r < 8; ++r)
#pragma unroll
        for (int c = 0; c < 8; ++c) acc[r][c] = 0.0f;

    for (int ch = 0; ch < NCH; ++ch) {
        const int kk0 = ch * KT;
        __syncthreads();
        for (int id = tid; id < KT * 32; id += 256) {
            int kl = id >> 5, q = id & 31;
            int kk = kk0 + kl;
            int f = kk / MMAT, m = kk - MMAT * f;
            int nd = q >> 4, bloc = (q & 15) * 4;
            *(float4*)&Asm[kl][q * 4] = *(const float4*)&Zp[nd][m][f * BB + bloc];
        }
        for (int id = tid; id < KT * 32; id += 256) {
            int kl = id >> 5, o4 = id & 31;
            *(float4*)&Wsm[kl][o4 * 4] =
                *(const float4*)&W[(long)(kk0 + kl) * 128 + o4 * 4];
        }
        __syncthreads();
#pragma unroll 5
        for (int kl = 0; kl < KT; ++kl) {
            float4 a0 = *(const float4*)&Asm[kl][ty * 8];
            float4 a1 = *(const float4*)&Asm[kl][ty * 8 + 4];
            float4 w0 = *(const float4*)&Wsm[kl][tx * 8];
            float4 w1 = *(const float4*)&Wsm[kl][tx * 8 + 4];
            float a[8] = {a0.x, a0.y, a0.z, a0.w, a1.x, a1.y, a1.z, a1.w};
            float w[8] = {w0.x, w0.y, w0.z, w0.w, w1.x, w1.y, w1.z, w1.w};
#pragma unroll
            for (int r = 0; r < 8; ++r)
#pragma unroll
                for (int c = 0; c < 8; ++c)
                    acc[r][c] = fmaf(a[r], w[c], acc[r][c]);
        }
    }
    __syncthreads();   // reads of g_x0 rows n0,n0+1 done before overwrite

#pragma unroll
    for (int r = 0; r < 8; ++r) {
        int brow = ty * 8 + r;
        int n = n0 + (brow >> 6), b = brow & 63;
#pragma unroll
        for (int c = 0; c < 8; ++c) {
            int o = tx * 8 + c;
            float y = acc[r][c] + bias[o];
            float v = 1.0f / (1.0f + expf(-y));
            if (o < UU) {
                float h = hx[b * (NN * UU) + n * UU + o];
                g_x0[(long)n * FB + (DIN + o) * BB + b] = v * h;
            } else {
                g_u[((long)b * NN + n) * UU + (o - UU)] = v;
            }
        }
    }
}

// ---------------------------------------------------------------------------
// K6: gconv2 projection + tanh + GRU combine.  4 nodes/block, 8x8 microtile.
// dyn smem: Asm[KT][256] + Wsm[KT][64] = 70400 B
// ---------------------------------------------------------------------------
__global__ __launch_bounds__(256) void proj_gate2_kernel(
        const float* __restrict__ W, const float* __restrict__ bias,
        const float* __restrict__ hx, float* __restrict__ out) {
    extern __shared__ float psm[];
    float (*Asm)[256] = (float(*)[256])psm;
    float (*Wsm)[64]  = (float(*)[64])(psm + KT * 256);

    const int n0 = blockIdx.x * 4;
    const int tid = threadIdx.x;
    const int tx = tid & 7;    // o group: o = tx*8 + c
    const int ty = tid >> 3;   // brow group: brow = ty*8 + r (0..255)

    const float* Zp[4][MMAT];
#pragma unroll
    for (int nd = 0; nd < 4; ++nd) {
        long base = (long)(n0 + nd) * FB;
        Zp[nd][0] = g_x0 + base;   Zp[nd][1] = g_x1[0] + base;
        Zp[nd][2] = g_x2[0] + base; Zp[nd][3] = g_x1[1] + base;
        Zp[nd][4] = g_x2[1] + base;
    }

    float acc[8][8];
#pragma unroll
    for (int r = 0; r < 8; ++r)
#pragma unroll
        for (int c = 0; c < 8; ++c) acc[r][c] = 0.0f;

    for (int ch = 0; ch < NCH; ++ch) {
        const int kk0 = ch * KT;
        __syncthreads();
        for (int id = tid; id < KT * 64; id += 256) {
            int kl = id >> 6, q = id & 63;
            int kk = kk0 + kl;
            int f = kk / MMAT, m = kk - MMAT * f;
            int nd = q >> 4, bloc = (q & 15) * 4;
            *(float4*)&Asm[kl][q * 4] = *(const float4*)&Zp[nd][m][f * BB + bloc];
        }
        for (int id = tid; id < KT * 16; id += 256) {
            int kl = id >> 4, o4 = id & 15;
            *(float4*)&Wsm[kl][o4 * 4] =
                *(const float4*)&W[(long)(kk0 + kl) * UU + o4 * 4];
        }
        __syncthreads();
#pragma unroll 5
        for (int kl = 0; kl < KT; ++kl) {
            float4 a0 = *(const float4*)&Asm[kl][ty * 8];
            float4 a1 = *(const float4*)&Asm[kl][ty * 8 + 4];
            float4 w0 = *(const float4*)&Wsm[kl][tx * 8];
            float4 w1 = *(const float4*)&Wsm[kl][tx * 8 + 4];
            float a[8] = {a0.x, a0.y, a0.z, a0.w, a1.x, a1.y, a1.z, a1.w};
            float w[8] = {w0.x, w0.y, w0.z, w0.w, w1.x, w1.y, w1.z, w1.w};
#pragma unroll
            for (int r = 0; r < 8; ++r)
#pragma unroll
                for (int c = 0; c < 8; ++c)
                    acc[r][c] = fmaf(a[r], w[c], acc[r][c]);
        }
    }

#pragma unroll
    for (int r = 0; r < 8; ++r) {
        int brow = ty * 8 + r;
        int n = n0 + (brow >> 6), b = brow & 63;
#pragma unroll
        for (int c = 0; c < 8; ++c) {
            int o = tx * 8 + c;
            float y = acc[r][c] + bias[o];
            float cc = tanhf(y);
            long hidx = (long)b * (NN * UU) + n * UU + o;
            float u = g_u[((long)b * NN + n) * UU + o];
            float h = hx[hidx];
            out[hidx] = u * h + (1.0f - u) * cc;
        }
    }
}

// ---------------------------------------------------------------------------
extern "C" void kernel_launch(void* const* d_in, const int* in_sizes, int n_in,
                              void* d_out, int out_size) {
    const float* inputs = (const float*)d_in[0];
    const float* hx     = (const float*)d_in[1];
    const float* S0     = (const float*)d_in[2];
    const float* S1     = (const float*)d_in[3];
    const float* Wo     = (const float*)d_in[4];
    const float* bo     = (const float*)d_in[5];
    const float* Wu     = (const float*)d_in[6];
    const float* bu     = (const float*)d_in[7];
    float* out = (float*)d_out;

    const int P1_SMEM = KT * 128 * 4 * 2;            // 56320
    const int P2_SMEM = KT * 256 * 4 + KT * 64 * 4;  // 70400
    cudaFuncSetAttribute(diffuse_hmma_kernel,
                         cudaFuncAttributeMaxDynamicSharedMemorySize, SMEM_HM);
    cudaFuncSetAttribute(proj_gate1_kernel,
                         cudaFuncAttributeMaxDynamicSharedMemorySize, P1_SMEM);
    cudaFuncSetAttribute(proj_gate2_kernel,
                         cudaFuncAttributeMaxDynamicSharedMemorySize, P2_SMEM);

    dim3 tgrid(FB / 64, NN / 64);        // (66, 16)
    dim3 mgrid(FB / 128, NN / 128, 2);   // (33, 8, 2)

    build_x0_kernel<<<(NN * FB + 255) / 256, 256>>>(inputs, hx);
    splitS_kernel<<<dim3((NN * NN + 255) / 256, 2), 256>>>(S0, S1);

    // gconv 1
    tsplit_kernel<<<tgrid, 256>>>(0);
    diffuse_hmma_kernel<<<mgrid, 256, SMEM_HM>>>(1);
    tsplit_kernel<<<tgrid, 256>>>(1);
    tsplit_kernel<<<tgrid, 256>>>(2);
    diffuse_hmma_kernel<<<mgrid, 256, SMEM_HM>>>(2);
    proj_gate1_kernel<<<NN / 2, 256, P1_SMEM>>>(Wo, bo, hx);

    // gconv 2 (x0 hidden slice now holds r*hx)
    tsplit_kernel<<<tgrid, 256>>>(0);
    diffuse_hmma_kernel<<<mgrid, 256, SMEM_HM>>>(1);
    tsplit_kernel<<<tgrid, 256>>>(1);
    tsplit_kernel<<<tgrid, 256>>>(2);
    diffuse_hmma_kernel<<<mgrid, 256, SMEM_HM>>>(2);
    proj_gate2_kernel<<<NN / 4, 256, P2_SMEM>>>(Wu, bu, hx, out);
}